// round 13
// baseline (speedup 1.0000x reference)
#include <cuda_runtime.h>
#include <cstdint>

// ---------------------------------------------------------------------------
// CausalSelfAttentionWithBias: B=4, T=2048, C=1024, H=16, D=64
// tf32 mma.m16n8k8. GEMMs: R10 BK=32 2-stage cp.async, transposed-B (n-major),
// all-ldsm. Attention: R12 flash + V stored transposed [B,H,D,T] so PV
// fragments load via ldmatrix (no scalar V LDS).
// ---------------------------------------------------------------------------

#define TT 2048
#define HH 16

__device__ float g_q[4 * HH * TT * 64];
__device__ float g_k[4 * HH * TT * 64];
__device__ float g_v[4 * HH * 64 * TT];   // TRANSPOSED: [B,H,D,T]
__device__ float g_y[4 * TT * 1024];
__device__ float g_x[4 * TT * 1024];      // x rounded to tf32
__device__ float g_wa[3072 * 1024];       // W_attn^T [n][k], tf32-rounded
__device__ float g_wp[1024 * 1024];       // W_proj^T [n][k], tf32-rounded

__device__ __forceinline__ unsigned f2t(float x) {
    unsigned u; asm("cvt.rna.tf32.f32 %0, %1;" : "=r"(u) : "f"(x)); return u;
}
__device__ __forceinline__ void mma8(float* d, const unsigned* a, const unsigned* b) {
    asm volatile(
        "mma.sync.aligned.m16n8k8.row.col.f32.tf32.tf32.f32 "
        "{%0,%1,%2,%3}, {%4,%5,%6,%7}, {%8,%9}, {%0,%1,%2,%3};"
        : "+f"(d[0]), "+f"(d[1]), "+f"(d[2]), "+f"(d[3])
        : "r"(a[0]), "r"(a[1]), "r"(a[2]), "r"(a[3]), "r"(b[0]), "r"(b[1]));
}
__device__ __forceinline__ unsigned sptr(const void* p) {
    return (unsigned)__cvta_generic_to_shared(p);
}
__device__ __forceinline__ void ldsm4(unsigned* r, unsigned addr) {
    asm volatile("ldmatrix.sync.aligned.m8n8.x4.shared.b16 {%0,%1,%2,%3}, [%4];"
        : "=r"(r[0]), "=r"(r[1]), "=r"(r[2]), "=r"(r[3]) : "r"(addr));
}
__device__ __forceinline__ void cpa16(unsigned dst, const void* src) {
    asm volatile("cp.async.cg.shared.global [%0], [%1], 16;" :: "r"(dst), "l"(src));
}
__device__ __forceinline__ void cp_commit() {
    asm volatile("cp.async.commit_group;");
}
template <int N> __device__ __forceinline__ void cp_wait() {
    asm volatile("cp.async.wait_group %0;" :: "n"(N));
}

// ---------------------------------------------------------------------------
// Prepasses
// ---------------------------------------------------------------------------
__global__ void cvt_kernel(const float* __restrict__ src, float* __restrict__ dst, int n4)
{
    int i = blockIdx.x * blockDim.x + threadIdx.x;
    if (i < n4) {
        float4 v = ((const float4*)src)[i];
        v.x = __uint_as_float(f2t(v.x));
        v.y = __uint_as_float(f2t(v.y));
        v.z = __uint_as_float(f2t(v.z));
        v.w = __uint_as_float(f2t(v.w));
        ((float4*)dst)[i] = v;
    }
}

// combined weight transpose: bx<96 -> W_attn (K=1024,N=3072), else W_proj
__global__ void transpose_cvt2(const float* __restrict__ srcA, float* __restrict__ dstA,
                               const float* __restrict__ srcP, float* __restrict__ dstP)
{
    __shared__ float tile[32][33];
    int bx = blockIdx.x;
    const float* src; float* dst; int N;
    if (bx < 96) { src = srcA; dst = dstA; N = 3072; }
    else         { src = srcP; dst = dstP; N = 1024; bx -= 96; }
    const int K = 1024;
    const int n0 = bx * 32, k0 = blockIdx.y * 32;
    const int tx = threadIdx.x, ty = threadIdx.y;
    #pragma unroll
    for (int j = 0; j < 4; j++)
        tile[ty + j * 8][tx] = src[(size_t)(k0 + ty + j * 8) * N + n0 + tx];
    __syncthreads();
    #pragma unroll
    for (int j = 0; j < 4; j++)
        dst[(size_t)(n0 + ty + j * 8) * K + k0 + tx] =
            __uint_as_float(f2t(tile[tx][ty + j * 8]));
}

#define SA 36                 // smem row stride (words) for 32-k rows
#define A_STG (128 * SA)      // words per stage (A and B identical: 128 x 32)
#define GSMEM (4 * A_STG * 4) // 2 stages A + 2 stages B = 73728 bytes

// ---------------------------------------------------------------------------
// GEMM core (R10, proven): 128x128 CTA tile, BK=32, 2-stage cp.async,
// 8 warps (2x4), warp tile 64x32, A and B fragments via ldmatrix (B n-major).
// ---------------------------------------------------------------------------
#define GEMM_BODY(Ag_, Bg_)                                                     \
    extern __shared__ unsigned dynsm_g[];                                       \
    unsigned* As = dynsm_g;                                                     \
    unsigned* Bs = dynsm_g + 2 * A_STG;                                         \
    const int tid = threadIdx.x;                                                \
    const int wid = tid >> 5, lane = tid & 31;                                  \
    const int mBase = (wid >> 2) * 64, nBase = (wid & 3) * 32;                  \
    const int g = lane >> 2, t = lane & 3;                                      \
    float acc[4][4][4] = {};                                                    \
    const unsigned sAs = sptr(As), sBs = sptr(Bs);                              \
    const int rA = (lane & 7) + ((lane >> 3) & 1) * 8;                          \
    const int kA = ((lane >> 4) & 1) * 4;                                       \
    const unsigned aOff = (mBase + rA) * SA + kA;                               \
    const int rB = (lane & 7) + ((lane >> 4) & 1) * 8;                          \
    const int kB = ((lane >> 3) & 1) * 4;                                       \
    const unsigned bOff = (nBase + rB) * SA + kB;                               \
    {                                                                           \
        _Pragma("unroll") for (int j = 0; j < 4; j++) {                         \
            int id = tid + j * 256, r = id >> 3, c4 = id & 7;                   \
            cpa16(sAs + (r * SA + c4 * 4) * 4, Ag_ + (size_t)r * 1024 + c4 * 4);\
            cpa16(sBs + (r * SA + c4 * 4) * 4, Bg_ + (size_t)r * 1024 + c4 * 4);\
        }                                                                       \
        cp_commit();                                                            \
    }                                                                           \
    for (int i = 0; i < 32; i++) {                                              \
        const int s = i & 1;                                                    \
        if (i + 1 < 32) {                                                       \
            const int kb = (i + 1) * 32;                                        \
            const unsigned so = (unsigned)(s ^ 1) * A_STG * 4;                  \
            _Pragma("unroll") for (int j = 0; j < 4; j++) {                     \
                int id = tid + j * 256, r = id >> 3, c4 = id & 7;               \
                cpa16(sAs + so + (r * SA + c4 * 4) * 4,                         \
                      Ag_ + (size_t)r * 1024 + kb + c4 * 4);                    \
                cpa16(sBs + so + (r * SA + c4 * 4) * 4,                         \
                      Bg_ + (size_t)r * 1024 + kb + c4 * 4);                    \
            }                                                                   \
            cp_commit();                                                        \
            cp_wait<1>();                                                       \
        } else {                                                                \
            cp_wait<0>();                                                       \
        }                                                                       \
        __syncthreads();                                                        \
        const unsigned aS = sAs + (unsigned)s * A_STG * 4;                      \
        const unsigned bS = sBs + (unsigned)s * A_STG * 4;                      \
        _Pragma("unroll")                                                       \
        for (int kk = 0; kk < 4; kk++) {                                        \
            const int k0 = kk * 8;                                              \
            unsigned af[4][4], bf[2][4];                                        \
            _Pragma("unroll")                                                   \
            for (int ii = 0; ii < 4; ii++)                                      \
                ldsm4(af[ii], aS + (aOff + ii * 16 * SA + k0) * 4);             \
            _Pragma("unroll")                                                   \
            for (int jp = 0; jp < 2; jp++)                                      \
                ldsm4(bf[jp], bS + (bOff + jp * 16 * SA + k0) * 4);             \
            _Pragma("unroll")                                                   \
            for (int ii = 0; ii < 4; ii++)                                      \
                _Pragma("unroll")                                               \
                for (int j = 0; j < 4; j++)                                     \
                    mma8(acc[ii][j], af[ii], &bf[j >> 1][(j & 1) * 2]);         \
        }                                                                       \
        __syncthreads();                                                        \
    }

// ---------------------------------------------------------------------------
// Stage 1: QKV GEMM (M=8192, K=1024, N=3072). grid (24, 64)
// Q/K scatter to [B,H,T,D]; V scatter TRANSPOSED to [B,H,D,T].
// ---------------------------------------------------------------------------
__global__ __launch_bounds__(256, 2)
void gemm_qkv_kernel(const float* __restrict__ b_attn,
                     const float* __restrict__ bQ,
                     const float* __restrict__ bK,
                     const float* __restrict__ bV)
{
    const int cRow = blockIdx.y, cCol = blockIdx.x;
    const float* Ag = g_x + (size_t)cRow * 128 * 1024;
    const float* Bg = g_wa + (size_t)cCol * 128 * 1024;

    GEMM_BODY(Ag, Bg)

    const int colW  = cCol * 128 + nBase;
    const int which = colW >> 10;
    const int h     = (colW & 1023) >> 6;

    if (which == 2) {
        // V: write transposed [B,H,D,T]
        const float* hb = bV + h * 64;
        #pragma unroll
        for (int j = 0; j < 4; j++) {
            int col = colW + j * 8 + t * 2;
            int d0 = col & 63;
            float bb0 = b_attn[col]     + hb[d0];
            float bb1 = b_attn[col + 1] + hb[d0 + 1];
            #pragma unroll
            for (int ii = 0; ii < 4; ii++) {
                int row0 = cRow * 128 + mBase + ii * 16 + g;
                #pragma unroll
                for (int rh = 0; rh < 2; rh++) {
                    int row = row0 + rh * 8;
                    int b = row >> 11, tt_ = row & 2047;
                    float v0 = __uint_as_float(f2t(acc[ii][j][rh * 2 + 0] + bb0));
                    float v1 = __uint_as_float(f2t(acc[ii][j][rh * 2 + 1] + bb1));
                    float* vb = g_v + ((size_t)(b * HH + h) * 64) * TT + tt_;
                    vb[(size_t)d0 * TT]       = v0;
                    vb[(size_t)(d0 + 1) * TT] = v1;
                }
            }
        }
    } else {
        float* dstBase  = which == 0 ? g_q : g_k;
        const float* hb = (which == 0 ? bQ : bK) + h * 64;
        const float scale = (which == 0) ? 0.125f : 1.0f;
        #pragma unroll
        for (int j = 0; j < 4; j++) {
            int col = colW + j * 8 + t * 2;
            int d0 = col & 63;
            float bb0 = (b_attn[col]     + hb[d0])     * scale;
            float bb1 = (b_attn[col + 1] + hb[d0 + 1]) * scale;
            #pragma unroll
            for (int ii = 0; ii < 4; ii++) {
                int row0 = cRow * 128 + mBase + ii * 16 + g;
                #pragma unroll
                for (int rh = 0; rh < 2; rh++) {
                    int row = row0 + rh * 8;
                    int b = row >> 11, tt_ = row & 2047;
                    float2 o;
                    o.x = __uint_as_float(f2t(acc[ii][j][rh * 2 + 0] * scale + bb0));
                    o.y = __uint_as_float(f2t(acc[ii][j][rh * 2 + 1] * scale + bb1));
                    *(float2*)(dstBase + (((size_t)(b * HH + h) * TT + tt_) << 6) + d0) = o;
                }
            }
        }
    }
}

// ---------------------------------------------------------------------------
// Stage 3: proj GEMM (M=8192, K=1024, N=1024). grid (8, 64)
// ---------------------------------------------------------------------------
__global__ __launch_bounds__(256, 2)
void gemm_proj_kernel(const float* __restrict__ b_proj,
                      float* __restrict__ out)
{
    const int cRow = blockIdx.y, cCol = blockIdx.x;
    const float* Ag = g_y + (size_t)cRow * 128 * 1024;
    const float* Bg = g_wp + (size_t)cCol * 128 * 1024;

    GEMM_BODY(Ag, Bg)

    #pragma unroll
    for (int j = 0; j < 4; j++) {
        int col = cCol * 128 + nBase + j * 8 + t * 2;
        float bb0 = b_proj[col], bb1 = b_proj[col + 1];
        #pragma unroll
        for (int ii = 0; ii < 4; ii++) {
            int row0 = cRow * 128 + mBase + ii * 16 + g;
            #pragma unroll
            for (int rh = 0; rh < 2; rh++) {
                int row = row0 + rh * 8;
                float2 o;
                o.x = acc[ii][j][rh * 2 + 0] + bb0;
                o.y = acc[ii][j][rh * 2 + 1] + bb1;
                *(float2*)(out + (size_t)row * 1024 + col) = o;
            }
        }
    }
}

// ---------------------------------------------------------------------------
// Stage 2: causal flash attention. K and V^T both fed via ldmatrix.
// ---------------------------------------------------------------------------
#define SQ 68    // Ks/Ps/Vs row stride (LDSM conflict-free)

__global__ __launch_bounds__(128)
void attn_kernel()
{
    __shared__ unsigned Ks[64 * SQ];   // [kv][d]; aliased as per-warp P after S
    __shared__ unsigned Vs[64 * SQ];   // [d][kv]  (V transposed)

    const int tid = threadIdx.x;
    const int w = tid >> 5, lane = tid & 31;
    const int g = lane >> 2, t = lane & 3;
    const int bh = blockIdx.y;
    const int qt = (int)gridDim.x - 1 - (int)blockIdx.x;  // long CTAs first
    const int q0 = qt * 64;

    const float* qbase = g_q + (size_t)bh * TT * 64;
    const float* kbase = g_k + (size_t)bh * TT * 64;
    const float* vbase = g_v + (size_t)bh * 64 * TT;      // [d][T]

    unsigned qa[8][4];
    {
        const float* q0p = qbase + (size_t)(q0 + w * 16 + g) * 64;
        const float* q1p = q0p + 8 * 64;
        #pragma unroll
        for (int kk = 0; kk < 8; kk++) {
            qa[kk][0] = __float_as_uint(q0p[kk * 8 + t]);
            qa[kk][1] = __float_as_uint(q1p[kk * 8 + t]);
            qa[kk][2] = __float_as_uint(q0p[kk * 8 + t + 4]);
            qa[kk][3] = __float_as_uint(q1p[kk * 8 + t + 4]);
        }
    }

    float oacc[8][4] = {};
    float mrow[2] = {-1e30f, -1e30f};
    float lrow[2] = {0.f, 0.f};

    unsigned* Psw = Ks + w * 16 * SQ;
    const unsigned sKs = sptr(Ks), sVs = sptr(Vs);

    // B-operand ldsm lane mapping (shared by K and V^T)
    const int rBf = (lane & 7) + ((lane >> 4) & 1) * 8;
    const int kBf = ((lane >> 3) & 1) * 4;
    const unsigned kAddr = sKs + (rBf * SQ + kBf) * 4;
    const unsigned vAddr = sVs + (rBf * SQ + kBf) * 4;
    // A-operand ldsm lane mapping (P)
    const int rAf = (lane & 7) + ((lane >> 3) & 1) * 8;
    const int kAf = ((lane >> 4) & 1) * 4;
    const unsigned pAddr = sptr(Psw) + (rAf * SQ + kAf) * 4;

    for (int tI = 0; tI <= qt; tI++) {
        __syncthreads();   // prior tile's P/V readers done
        const float* kt = kbase + (size_t)tI * 64 * 64;
        const float* vt = vbase + (size_t)tI * 64;        // col offset in [d][T]
        // K group first, V group second (V overlaps S-compute)
        #pragma unroll
        for (int i = 0; i < 8; i++) {
            int id = tid + i * 128;
            int r = id >> 4, c4 = id & 15;
            cpa16(sKs + (r * SQ + c4 * 4) * 4, kt + r * 64 + c4 * 4);
        }
        cp_commit();
        #pragma unroll
        for (int i = 0; i < 8; i++) {
            int id = tid + i * 128;
            int r = id >> 4, c4 = id & 15;   // r = d row, c4*4 = kv offset
            cpa16(sVs + (r * SQ + c4 * 4) * 4, vt + (size_t)r * TT + c4 * 4);
        }
        cp_commit();
        cp_wait<1>();      // K arrived; V still in flight
        __syncthreads();

        // S = Q . K^T  (V loads under this)
        float sacc[8][4] = {};
        #pragma unroll
        for (int kk = 0; kk < 8; kk++) {
            const int k0 = kk * 8;
            #pragma unroll
            for (int jp = 0; jp < 4; jp++) {
                unsigned kf[4];
                ldsm4(kf, kAddr + (jp * 16 * SQ + k0) * 4);
                mma8(sacc[jp * 2 + 0], qa[kk], &kf[0]);
                mma8(sacc[jp * 2 + 1], qa[kk], &kf[2]);
            }
        }
        cp_wait<0>();      // V arrived
        __syncthreads();   // Ks reads done (P alias) + V visible to all

        if (tI == qt) {
            #pragma unroll
            for (int j = 0; j < 8; j++)
                #pragma unroll
                for (int r = 0; r < 4; r++) {
                    int rq = w * 16 + g + (r >> 1) * 8;
                    int cq = j * 8 + t * 2 + (r & 1);
                    if (cq > rq) sacc[j][r] = -1e30f;
                }
        }

        float corr[2];
        #pragma unroll
        for (int rh = 0; rh < 2; rh++) {
            float mt = -1e30f;
            #pragma unroll
            for (int j = 0; j < 8; j++)
                mt = fmaxf(mt, fmaxf(sacc[j][rh * 2], sacc[j][rh * 2 + 1]));
            mt = fmaxf(mt, __shfl_xor_sync(0xffffffffu, mt, 1));
            mt = fmaxf(mt, __shfl_xor_sync(0xffffffffu, mt, 2));
            float mn = fmaxf(mrow[rh], mt);
            corr[rh] = __expf(mrow[rh] - mn);
            mrow[rh] = mn;
        }
        float ls0 = 0.f, ls1 = 0.f;
        #pragma unroll
        for (int j = 0; j < 8; j++) {
            float p0 = __expf(sacc[j][0] - mrow[0]);
            float p1 = __expf(sacc[j][1] - mrow[0]);
            float p2 = __expf(sacc[j][2] - mrow[1]);
            float p3 = __expf(sacc[j][3] - mrow[1]);
            sacc[j][0] = p0; sacc[j][1] = p1; sacc[j][2] = p2; sacc[j][3] = p3;
            ls0 += p0 + p1; ls1 += p2 + p3;
        }
        ls0 += __shfl_xor_sync(0xffffffffu, ls0, 1);
        ls0 += __shfl_xor_sync(0xffffffffu, ls0, 2);
        ls1 += __shfl_xor_sync(0xffffffffu, ls1, 1);
        ls1 += __shfl_xor_sync(0xffffffffu, ls1, 2);
        lrow[0] = lrow[0] * corr[0] + ls0;
        lrow[1] = lrow[1] * corr[1] + ls1;

        #pragma unroll
        for (int j = 0; j < 8; j++) {
            oacc[j][0] *= corr[0]; oacc[j][1] *= corr[0];
            oacc[j][2] *= corr[1]; oacc[j][3] *= corr[1];
        }

        #pragma unroll
        for (int j = 0; j < 8; j++) {
            unsigned* p0 = &Psw[g * SQ + j * 8 + t * 2];
            p0[0] = f2t(sacc[j][0]); p0[1] = f2t(sacc[j][1]);
            unsigned* p1 = &Psw[(g + 8) * SQ + j * 8 + t * 2];
            p1[0] = f2t(sacc[j][2]); p1[1] = f2t(sacc[j][3]);
        }
        __syncwarp();

        // O += P . V   (P A-frag and V^T B-frag both via ldmatrix)
        #pragma unroll
        for (int kk = 0; kk < 8; kk++) {
            const int k0 = kk * 8;
            unsigned pa[4];
            ldsm4(pa, pAddr + k0 * 4);
            #pragma unroll
            for (int jp = 0; jp < 4; jp++) {
                unsigned vf[4];
                ldsm4(vf, vAddr + (jp * 16 * SQ + k0) * 4);
                mma8(oacc[jp * 2 + 0], pa, &vf[0]);
                mma8(oacc[jp * 2 + 1], pa, &vf[2]);
            }
        }
    }

    const int b = bh >> 4, h = bh & 15;
    const float inv0 = 1.f / lrow[0], inv1 = 1.f / lrow[1];
    float* yb = g_y + ((size_t)b * TT + q0 + w * 16) * 1024 + h * 64;
    #pragma unroll
    for (int j = 0; j < 8; j++) {
        float2 o0, o1;
        o0.x = __uint_as_float(f2t(oacc[j][0] * inv0));
        o0.y = __uint_as_float(f2t(oacc[j][1] * inv0));
        o1.x = __uint_as_float(f2t(oacc[j][2] * inv1));
        o1.y = __uint_as_float(f2t(oacc[j][3] * inv1));
        *(float2*)(yb + (size_t)g * 1024 + j * 8 + t * 2) = o0;
        *(float2*)(yb + (size_t)(g + 8) * 1024 + j * 8 + t * 2) = o1;
    }
}

// ---------------------------------------------------------------------------
extern "C" void kernel_launch(void* const* d_in, const int* in_sizes, int n_in,
                              void* d_out, int out_size)
{
    (void)in_sizes; (void)n_in; (void)out_size;
    const float* x      = (const float*)d_in[0];
    const float* W_attn = (const float*)d_in[1];
    const float* b_attn = (const float*)d_in[2];
    const float* W_proj = (const float*)d_in[3];
    const float* b_proj = (const float*)d_in[4];
    const float* bQ     = (const float*)d_in[5];
    const float* bK     = (const float*)d_in[6];
    const float* bV     = (const float*)d_in[7];
    float* out = (float*)d_out;

    cudaFuncSetAttribute(gemm_qkv_kernel,
                         cudaFuncAttributeMaxDynamicSharedMemorySize, GSMEM);
    cudaFuncSetAttribute(gemm_proj_kernel,
                         cudaFuncAttributeMaxDynamicSharedMemorySize, GSMEM);

    float *p_x, *p_wa, *p_wp;
    cudaGetSymbolAddress((void**)&p_x,  g_x);
    cudaGetSymbolAddress((void**)&p_wa, g_wa);
    cudaGetSymbolAddress((void**)&p_wp, g_wp);

    // prepass: round x; transpose+round both weights (one launch)
    cvt_kernel<<<(2097152 + 255) / 256, 256>>>(x, p_x, 2097152);
    transpose_cvt2<<<dim3(128, 32), dim3(32, 8)>>>(W_attn, p_wa, W_proj, p_wp);

    gemm_qkv_kernel<<<dim3(24, 64), 256, GSMEM>>>(b_attn, bQ, bK, bV);

    attn_kernel<<<dim3(TT / 64, 4 * HH), 128>>>();

    gemm_proj_kernel<<<dim3(8, 64), 256, GSMEM>>>(b_proj, out);
}

// round 15
// speedup vs baseline: 1.0241x; 1.0241x over previous
#include <cuda_runtime.h>
#include <cstdint>

// ---------------------------------------------------------------------------
// CausalSelfAttentionWithBias: B=4, T=2048, C=1024, H=16, D=64
// tf32 mma.m16n8k8. GEMMs: R10 BK=32 2-stage cp.async, transposed-B (n-major),
// all-ldsm. Attention: R12 flash + double-buffered K/V (fixed fill mapping).
// ---------------------------------------------------------------------------

#define TT 2048
#define HH 16

__device__ float g_q[4 * HH * TT * 64];
__device__ float g_k[4 * HH * TT * 64];
__device__ float g_v[4 * HH * TT * 64];
__device__ float g_y[4 * TT * 1024];
__device__ float g_x[4 * TT * 1024];      // x rounded to tf32
__device__ float g_wa[3072 * 1024];       // W_attn^T [n][k], tf32-rounded
__device__ float g_wp[1024 * 1024];       // W_proj^T [n][k], tf32-rounded

__device__ __forceinline__ unsigned f2t(float x) {
    unsigned u; asm("cvt.rna.tf32.f32 %0, %1;" : "=r"(u) : "f"(x)); return u;
}
__device__ __forceinline__ void mma8(float* d, const unsigned* a, const unsigned* b) {
    asm volatile(
        "mma.sync.aligned.m16n8k8.row.col.f32.tf32.tf32.f32 "
        "{%0,%1,%2,%3}, {%4,%5,%6,%7}, {%8,%9}, {%0,%1,%2,%3};"
        : "+f"(d[0]), "+f"(d[1]), "+f"(d[2]), "+f"(d[3])
        : "r"(a[0]), "r"(a[1]), "r"(a[2]), "r"(a[3]), "r"(b[0]), "r"(b[1]));
}
__device__ __forceinline__ unsigned sptr(const void* p) {
    return (unsigned)__cvta_generic_to_shared(p);
}
__device__ __forceinline__ void ldsm4(unsigned* r, unsigned addr) {
    asm volatile("ldmatrix.sync.aligned.m8n8.x4.shared.b16 {%0,%1,%2,%3}, [%4];"
        : "=r"(r[0]), "=r"(r[1]), "=r"(r[2]), "=r"(r[3]) : "r"(addr));
}
__device__ __forceinline__ void cpa16(unsigned dst, const void* src) {
    asm volatile("cp.async.cg.shared.global [%0], [%1], 16;" :: "r"(dst), "l"(src));
}
__device__ __forceinline__ void cp_commit() {
    asm volatile("cp.async.commit_group;");
}
template <int N> __device__ __forceinline__ void cp_wait() {
    asm volatile("cp.async.wait_group %0;" :: "n"(N));
}

// ---------------------------------------------------------------------------
// Fused prepass: blocks [0,8192) round x; blocks [8192,12288) transpose+round
// W_attn (first 96 of every 128 x-tiles) and W_proj (last 32).
// ---------------------------------------------------------------------------
__global__ void prepass_kernel(const float* __restrict__ x,      float* __restrict__ px,
                               const float* __restrict__ srcA,   float* __restrict__ dstA,
                               const float* __restrict__ srcP,   float* __restrict__ dstP)
{
    __shared__ float tile[32][33];
    const int bx = blockIdx.x;
    if (bx < 8192) {
        int i = bx * 256 + threadIdx.x;
        float4 v = ((const float4*)x)[i];
        v.x = __uint_as_float(f2t(v.x));
        v.y = __uint_as_float(f2t(v.y));
        v.z = __uint_as_float(f2t(v.z));
        v.w = __uint_as_float(f2t(v.w));
        ((float4*)px)[i] = v;
        return;
    }
    int b = bx - 8192;                 // 0..4095
    int bxx = b & 127, byy = b >> 7;   // 128 x 32
    const float* src; float* dst; int N;
    if (bxx < 96) { src = srcA; dst = dstA; N = 3072; }
    else          { src = srcP; dst = dstP; N = 1024; bxx -= 96; }
    const int K = 1024;
    const int n0 = bxx * 32, k0 = byy * 32;
    const int tx = threadIdx.x & 31, ty = threadIdx.x >> 5;   // 32 x 8
    #pragma unroll
    for (int j = 0; j < 4; j++)
        tile[ty + j * 8][tx] = src[(size_t)(k0 + ty + j * 8) * N + n0 + tx];
    __syncthreads();
    #pragma unroll
    for (int j = 0; j < 4; j++)
        dst[(size_t)(n0 + ty + j * 8) * K + k0 + tx] =
            __uint_as_float(f2t(tile[tx][ty + j * 8]));
}

#define SA 36                 // smem row stride (words) for 32-k rows
#define A_STG (128 * SA)      // words per stage (A and B identical: 128 x 32)
#define GSMEM (4 * A_STG * 4) // 2 stages A + 2 stages B = 73728 bytes

// ---------------------------------------------------------------------------
// GEMM core (R10, proven): 128x128 CTA tile, BK=32, 2-stage cp.async,
// 8 warps (2x4), warp tile 64x32, A and B fragments via ldmatrix (B n-major).
// ---------------------------------------------------------------------------
#define GEMM_BODY(Ag_, Bg_)                                                     \
    extern __shared__ unsigned dynsm_g[];                                       \
    unsigned* As = dynsm_g;                                                     \
    unsigned* Bs = dynsm_g + 2 * A_STG;                                         \
    const int tid = threadIdx.x;                                                \
    const int wid = tid >> 5, lane = tid & 31;                                  \
    const int mBase = (wid >> 2) * 64, nBase = (wid & 3) * 32;                  \
    const int g = lane >> 2, t = lane & 3;                                      \
    float acc[4][4][4] = {};                                                    \
    const unsigned sAs = sptr(As), sBs = sptr(Bs);                              \
    const int rA = (lane & 7) + ((lane >> 3) & 1) * 8;                          \
    const int kA = ((lane >> 4) & 1) * 4;                                       \
    const unsigned aOff = (mBase + rA) * SA + kA;                               \
    const int rB = (lane & 7) + ((lane >> 4) & 1) * 8;                          \
    const int kB = ((lane >> 3) & 1) * 4;                                       \
    const unsigned bOff = (nBase + rB) * SA + kB;                               \
    {                                                                           \
        _Pragma("unroll") for (int j = 0; j < 4; j++) {                         \
            int id = tid + j * 256, r = id >> 3, c4 = id & 7;                   \
            cpa16(sAs + (r * SA + c4 * 4) * 4, Ag_ + (size_t)r * 1024 + c4 * 4);\
            cpa16(sBs + (r * SA + c4 * 4) * 4, Bg_ + (size_t)r * 1024 + c4 * 4);\
        }                                                                       \
        cp_commit();                                                            \
    }                                                                           \
    for (int i = 0; i < 32; i++) {                                              \
        const int s = i & 1;                                                    \
        if (i + 1 < 32) {                                                       \
            const int kb = (i + 1) * 32;                                        \
            const unsigned so = (unsigned)(s ^ 1) * A_STG * 4;                  \
            _Pragma("unroll") for (int j = 0; j < 4; j++) {                     \
                int id = tid + j * 256, r = id >> 3, c4 = id & 7;               \
                cpa16(sAs + so + (r * SA + c4 * 4) * 4,                         \
                      Ag_ + (size_t)r * 1024 + kb + c4 * 4);                    \
                cpa16(sBs + so + (r * SA + c4 * 4) * 4,                         \
                      Bg_ + (size_t)r * 1024 + kb + c4 * 4);                    \
            }                                                                   \
            cp_commit();                                                        \
            cp_wait<1>();                                                       \
        } else {                                                                \
            cp_wait<0>();                                                       \
        }                                                                       \
        __syncthreads();                                                        \
        const unsigned aS = sAs + (unsigned)s * A_STG * 4;                      \
        const unsigned bS = sBs + (unsigned)s * A_STG * 4;                      \
        _Pragma("unroll")                                                       \
        for (int kk = 0; kk < 4; kk++) {                                        \
            const int k0 = kk * 8;                                              \
            unsigned af[4][4], bf[2][4];                                        \
            _Pragma("unroll")                                                   \
            for (int ii = 0; ii < 4; ii++)                                      \
                ldsm4(af[ii], aS + (aOff + ii * 16 * SA + k0) * 4);             \
            _Pragma("unroll")                                                   \
            for (int jp = 0; jp < 2; jp++)                                      \
                ldsm4(bf[jp], bS + (bOff + jp * 16 * SA + k0) * 4);             \
            _Pragma("unroll")                                                   \
            for (int ii = 0; ii < 4; ii++)                                      \
                _Pragma("unroll")                                               \
                for (int j = 0; j < 4; j++)                                     \
                    mma8(acc[ii][j], af[ii], &bf[j >> 1][(j & 1) * 2]);         \
        }                                                                       \
        __syncthreads();                                                        \
    }

// ---------------------------------------------------------------------------
// Stage 1: QKV GEMM (M=8192, K=1024, N=3072). grid (24, 64)
// ---------------------------------------------------------------------------
__global__ __launch_bounds__(256, 2)
void gemm_qkv_kernel(const float* __restrict__ b_attn,
                     const float* __restrict__ bQ,
                     const float* __restrict__ bK,
                     const float* __restrict__ bV)
{
    const int cRow = blockIdx.y, cCol = blockIdx.x;
    const float* Ag = g_x + (size_t)cRow * 128 * 1024;
    const float* Bg = g_wa + (size_t)cCol * 128 * 1024;

    GEMM_BODY(Ag, Bg)

    const int colW  = cCol * 128 + nBase;
    const int which = colW >> 10;
    const int h     = (colW & 1023) >> 6;
    float* dstBase  = which == 0 ? g_q : (which == 1 ? g_k : g_v);
    const float* hb = (which == 0 ? bQ : (which == 1 ? bK : bV)) + h * 64;
    const float scale = (which == 0) ? 0.125f : 1.0f;

    #pragma unroll
    for (int j = 0; j < 4; j++) {
        int col = colW + j * 8 + t * 2;
        int d0 = col & 63;
        float bb0 = (b_attn[col]     + hb[d0])     * scale;
        float bb1 = (b_attn[col + 1] + hb[d0 + 1]) * scale;
        #pragma unroll
        for (int ii = 0; ii < 4; ii++) {
            int row0 = cRow * 128 + mBase + ii * 16 + g;
            #pragma unroll
            for (int rh = 0; rh < 2; rh++) {
                int row = row0 + rh * 8;
                int b = row >> 11, tt_ = row & 2047;
                float2 o;
                o.x = __uint_as_float(f2t(acc[ii][j][rh * 2 + 0] * scale + bb0));
                o.y = __uint_as_float(f2t(acc[ii][j][rh * 2 + 1] * scale + bb1));
                *(float2*)(dstBase + (((size_t)(b * HH + h) * TT + tt_) << 6) + d0) = o;
            }
        }
    }
}

// ---------------------------------------------------------------------------
// Stage 3: proj GEMM (M=8192, K=1024, N=1024). grid (8, 64)
// ---------------------------------------------------------------------------
__global__ __launch_bounds__(256, 2)
void gemm_proj_kernel(const float* __restrict__ b_proj,
                      float* __restrict__ out)
{
    const int cRow = blockIdx.y, cCol = blockIdx.x;
    const float* Ag = g_y + (size_t)cRow * 128 * 1024;
    const float* Bg = g_wp + (size_t)cCol * 128 * 1024;

    GEMM_BODY(Ag, Bg)

    #pragma unroll
    for (int j = 0; j < 4; j++) {
        int col = cCol * 128 + nBase + j * 8 + t * 2;
        float bb0 = b_proj[col], bb1 = b_proj[col + 1];
        #pragma unroll
        for (int ii = 0; ii < 4; ii++) {
            int row0 = cRow * 128 + mBase + ii * 16 + g;
            #pragma unroll
            for (int rh = 0; rh < 2; rh++) {
                int row = row0 + rh * 8;
                float2 o;
                o.x = acc[ii][j][rh * 2 + 0] + bb0;
                o.y = acc[ii][j][rh * 2 + 1] + bb1;
                *(float2*)(out + (size_t)row * 1024 + col) = o;
            }
        }
    }
}

// ---------------------------------------------------------------------------
// Stage 2: causal flash attention (R12 + double-buffered K/V).
// stage s at word offset s*KV_STG: [K 64xSQ | V 64xSV]; P aliases K of the
// CURRENT stage after the post-S barrier; prefetch targets the other stage.
// Fill mapping: 8 rounds of (tid + i*128) covering all 64 rows x 16 chunks.
// ---------------------------------------------------------------------------
#define SQ 68
#define SV 72
#define KV_STG (64 * SQ + 64 * SV)
#define ATT_SMEM (2 * KV_STG * 4)     // 71680 bytes

__global__ __launch_bounds__(128)
void attn_kernel()
{
    extern __shared__ unsigned asm_sm[];

    const int tid = threadIdx.x;
    const int w = tid >> 5, lane = tid & 31;
    const int g = lane >> 2, t = lane & 3;
    const int bh = blockIdx.y;
    const int qt = (int)gridDim.x - 1 - (int)blockIdx.x;  // long CTAs first
    const int q0 = qt * 64;

    const float* qbase = g_q + (size_t)bh * TT * 64;
    const float* kbase = g_k + (size_t)bh * TT * 64;
    const float* vbase = g_v + (size_t)bh * TT * 64;

    unsigned qa[8][4];
    {
        const float* q0p = qbase + (size_t)(q0 + w * 16 + g) * 64;
        const float* q1p = q0p + 8 * 64;
        #pragma unroll
        for (int kk = 0; kk < 8; kk++) {
            qa[kk][0] = __float_as_uint(q0p[kk * 8 + t]);
            qa[kk][1] = __float_as_uint(q1p[kk * 8 + t]);
            qa[kk][2] = __float_as_uint(q0p[kk * 8 + t + 4]);
            qa[kk][3] = __float_as_uint(q1p[kk * 8 + t + 4]);
        }
    }

    float oacc[8][4] = {};
    float mrow[2] = {-1e30f, -1e30f};
    float lrow[2] = {0.f, 0.f};

    const unsigned sBase = sptr(asm_sm);

    // fragment lane offsets (stage-relative, words)
    const int rBf = (lane & 7) + ((lane >> 4) & 1) * 8;
    const int kBf = ((lane >> 3) & 1) * 4;
    const unsigned kOffW = (unsigned)(rBf * SQ + kBf);
    const int rAf = (lane & 7) + ((lane >> 3) & 1) * 8;
    const int kAf = ((lane >> 4) & 1) * 4;
    const unsigned pOffW = (unsigned)(w * 16 * SQ + rAf * SQ + kAf);

    // fill mapping: 8 rounds x 128 threads = 64 rows x 16 float4-chunks
    #define ATT_FILL(tile_, st_)                                                \
        {                                                                       \
            const float* kt_ = kbase + (size_t)(tile_) * 64 * 64;               \
            const float* vt_ = vbase + (size_t)(tile_) * 64 * 64;               \
            const unsigned kd_ = sBase + ((unsigned)(st_) * KV_STG) * 4;        \
            const unsigned vd_ = kd_ + (64 * SQ) * 4;                           \
            _Pragma("unroll")                                                   \
            for (int i_ = 0; i_ < 8; i_++) {                                    \
                int id_ = tid + i_ * 128;                                       \
                int r_ = id_ >> 4, c4_ = (id_ & 15) * 4;                        \
                cpa16(kd_ + (r_ * SQ + c4_) * 4, kt_ + r_ * 64 + c4_);          \
                cpa16(vd_ + (r_ * SV + c4_) * 4, vt_ + r_ * 64 + c4_);          \
            }                                                                   \
            cp_commit();                                                        \
        }

    ATT_FILL(0, 0)

    for (int tI = 0; tI <= qt; tI++) {
        const int s = tI & 1;
        const unsigned stgB = (unsigned)s * KV_STG;          // words
        const unsigned kAddr = sBase + (stgB + kOffW) * 4;
        const unsigned pAddr = sBase + (stgB + pOffW) * 4;
        unsigned* Psw = asm_sm + stgB + w * 16 * SQ;
        const unsigned* Vs = asm_sm + stgB + 64 * SQ;

        __syncthreads();             // stage s^1 readers (tile tI-1) done
        if (tI < qt) {
            ATT_FILL(tI + 1, s ^ 1)
            cp_wait<1>();
        } else {
            cp_wait<0>();
        }
        __syncthreads();             // stage s visible to all

        // S = Q . K^T
        float sacc[8][4] = {};
        #pragma unroll
        for (int kk = 0; kk < 8; kk++) {
            const int k0 = kk * 8;
            #pragma unroll
            for (int jp = 0; jp < 4; jp++) {
                unsigned kf[4];
                ldsm4(kf, kAddr + (jp * 16 * SQ + k0) * 4);
                mma8(sacc[jp * 2 + 0], qa[kk], &kf[0]);
                mma8(sacc[jp * 2 + 1], qa[kk], &kf[2]);
            }
        }

        if (tI == qt) {
            #pragma unroll
            for (int j = 0; j < 8; j++)
                #pragma unroll
                for (int r = 0; r < 4; r++) {
                    int rq = w * 16 + g + (r >> 1) * 8;
                    int cq = j * 8 + t * 2 + (r & 1);
                    if (cq > rq) sacc[j][r] = -1e30f;
                }
        }

        // online softmax (registers only)
        float corr[2];
        #pragma unroll
        for (int rh = 0; rh < 2; rh++) {
            float mt = -1e30f;
            #pragma unroll
            for (int j = 0; j < 8; j++)
                mt = fmaxf(mt, fmaxf(sacc[j][rh * 2], sacc[j][rh * 2 + 1]));
            mt = fmaxf(mt, __shfl_xor_sync(0xffffffffu, mt, 1));
            mt = fmaxf(mt, __shfl_xor_sync(0xffffffffu, mt, 2));
            float mn = fmaxf(mrow[rh], mt);
            corr[rh] = __expf(mrow[rh] - mn);
            mrow[rh] = mn;
        }
        float ls0 = 0.f, ls1 = 0.f;
        #pragma unroll
        for (int j = 0; j < 8; j++) {
            float p0 = __expf(sacc[j][0] - mrow[0]);
            float p1 = __expf(sacc[j][1] - mrow[0]);
            float p2 = __expf(sacc[j][2] - mrow[1]);
            float p3 = __expf(sacc[j][3] - mrow[1]);
            sacc[j][0] = p0; sacc[j][1] = p1; sacc[j][2] = p2; sacc[j][3] = p3;
            ls0 += p0 + p1; ls1 += p2 + p3;
        }
        ls0 += __shfl_xor_sync(0xffffffffu, ls0, 1);
        ls0 += __shfl_xor_sync(0xffffffffu, ls0, 2);
        ls1 += __shfl_xor_sync(0xffffffffu, ls1, 1);
        ls1 += __shfl_xor_sync(0xffffffffu, ls1, 2);
        lrow[0] = lrow[0] * corr[0] + ls0;
        lrow[1] = lrow[1] * corr[1] + ls1;

        #pragma unroll
        for (int j = 0; j < 8; j++) {
            oacc[j][0] *= corr[0]; oacc[j][1] *= corr[0];
            oacc[j][2] *= corr[1]; oacc[j][3] *= corr[1];
        }

        __syncthreads();             // all warps' S reads of Ks[s] done

        // P -> per-warp region of Ks[s]
        #pragma unroll
        for (int j = 0; j < 8; j++) {
            unsigned* p0 = &Psw[g * SQ + j * 8 + t * 2];
            p0[0] = f2t(sacc[j][0]); p0[1] = f2t(sacc[j][1]);
            unsigned* p1 = &Psw[(g + 8) * SQ + j * 8 + t * 2];
            p1[0] = f2t(sacc[j][2]); p1[1] = f2t(sacc[j][3]);
        }
        __syncwarp();

        // O += P . V
        #pragma unroll
        for (int kk = 0; kk < 8; kk++) {
            const int k0 = kk * 8;
            unsigned pa[4];
            ldsm4(pa, pAddr + k0 * 4);
            #pragma unroll
            for (int j = 0; j < 8; j++) {
                unsigned vb[2];
                vb[0] = Vs[(k0 + t) * SV + j * 8 + g];
                vb[1] = Vs[(k0 + t + 4) * SV + j * 8 + g];
                mma8(oacc[j], pa, vb);
            }
        }
    }
    #undef ATT_FILL

    const int b = bh >> 4, h = bh & 15;
    const float inv0 = 1.f / lrow[0], inv1 = 1.f / lrow[1];
    float* yb = g_y + ((size_t)b * TT + q0 + w * 16) * 1024 + h * 64;
    #pragma unroll
    for (int j = 0; j < 8; j++) {
        float2 o0, o1;
        o0.x = __uint_as_float(f2t(oacc[j][0] * inv0));
        o0.y = __uint_as_float(f2t(oacc[j][1] * inv0));
        o1.x = __uint_as_float(f2t(oacc[j][2] * inv1));
        o1.y = __uint_as_float(f2t(oacc[j][3] * inv1));
        *(float2*)(yb + (size_t)g * 1024 + j * 8 + t * 2) = o0;
        *(float2*)(yb + (size_t)(g + 8) * 1024 + j * 8 + t * 2) = o1;
    }
}

// ---------------------------------------------------------------------------
extern "C" void kernel_launch(void* const* d_in, const int* in_sizes, int n_in,
                              void* d_out, int out_size)
{
    (void)in_sizes; (void)n_in; (void)out_size;
    const float* x      = (const float*)d_in[0];
    const float* W_attn = (const float*)d_in[1];
    const float* b_attn = (const float*)d_in[2];
    const float* W_proj = (const float*)d_in[3];
    const float* b_proj = (const float*)d_in[4];
    const float* bQ     = (const float*)d_in[5];
    const float* bK     = (const float*)d_in[6];
    const float* bV     = (const float*)d_in[7];
    float* out = (float*)d_out;

    cudaFuncSetAttribute(gemm_qkv_kernel,
                         cudaFuncAttributeMaxDynamicSharedMemorySize, GSMEM);
    cudaFuncSetAttribute(gemm_proj_kernel,
                         cudaFuncAttributeMaxDynamicSharedMemorySize, GSMEM);
    cudaFuncSetAttribute(attn_kernel,
                         cudaFuncAttributeMaxDynamicSharedMemorySize, ATT_SMEM);

    float *p_x, *p_wa, *p_wp;
    cudaGetSymbolAddress((void**)&p_x,  g_x);
    cudaGetSymbolAddress((void**)&p_wa, g_wa);
    cudaGetSymbolAddress((void**)&p_wp, g_wp);

    // fused prepass: round x + transpose/round both weights, one launch
    prepass_kernel<<<8192 + 4096, 256>>>(x, p_x, W_attn, p_wa, W_proj, p_wp);

    gemm_qkv_kernel<<<dim3(24, 64), 256, GSMEM>>>(b_attn, bQ, bK, bV);

    attn_kernel<<<dim3(TT / 64, 4 * HH), 128, ATT_SMEM>>>();

    gemm_proj_kernel<<<dim3(8, 64), 256, GSMEM>>>(b_proj, out);
}